// round 16
// baseline (speedup 1.0000x reference)
#include <cuda_runtime.h>

#define NB 2000000
#define NCLS 10
#define KPRE 4096
#define KPOST 500
#define CAND_MAX 8192
#define NBKT 8192
#define NCELL 17
#define NCELLS (NCELL * NCELL)
#define CELLCAP 4096
#define EDGE_MAX_G 262144
#define EDGE_SH 4096
#define NTH 256
#define NBLK1 592
#define NTOT1 (NBLK1 * NTH)
#define IPT 4
#define NBLK2 400
#define NTOT2 (NBLK2 * NTH)

// -------- global scratch (zero-init at load; restored by in-kernel cleanup) --------
static __device__ unsigned g_hist1[4096];
static __device__ unsigned g_hist2v[4096];
static __device__ unsigned g_bcnt[NBKT];
static __device__ unsigned g_cellcnt[NCELLS];
static __device__ unsigned long long g_sorted[CAND_MAX];
static __device__ unsigned g_ncand, g_kmax, g_nedge;
static __device__ unsigned long long g_cand[CAND_MAX];
static __device__ unsigned g_topkey[KPRE];
static __device__ float g_bx1[KPRE], g_by1[KPRE], g_bx2[KPRE], g_by2[KPRE], g_area[KPRE];
static __device__ int g_lab[KPRE];
static __device__ unsigned long long g_valid[64];
static __device__ int g_cellid[KPRE];
static __device__ unsigned short g_cellbox[NCELLS * CELLCAP];
static __device__ unsigned g_edges[EDGE_MAX_G];
static __device__ volatile unsigned g_sync[8];

// grid barrier; all blocks co-resident (enforced by __launch_bounds__ + grid size)
__device__ __forceinline__ void gridsync(int id, int nblk) {
    __syncthreads();
    if (threadIdx.x == 0) {
        __threadfence();
        atomicAdd((unsigned*)&g_sync[id], 1u);
        unsigned ns = 64;
        while (g_sync[id] < (unsigned)nblk) {
            __nanosleep(ns);
            if (ns < 512) ns <<= 1;
        }
        __threadfence();
    }
    __syncthreads();
}

// block-level "find bucket containing rank (counted from top)" over a 4096 histogram
__device__ __forceinline__ void block_select(const unsigned* __restrict__ gh, unsigned rank,
                                             unsigned* part, unsigned* selb, unsigned* selr) {
    int t = threadIdx.x;
    if (t == 0) { *selb = 0; *selr = 1; }
    unsigned v[16];
    unsigned s = 0;
    #pragma unroll
    for (int q = 0; q < 16; q++) { v[q] = gh[t * 16 + q]; s += v[q]; }
    part[t] = s;
    __syncthreads();
    for (int d = 1; d < 256; d <<= 1) {
        unsigned x = part[t] + ((t + d < 256) ? part[t + d] : 0u);
        __syncthreads();
        part[t] = x;
        __syncthreads();
    }
    unsigned incl = part[t];
    unsigned above = incl - s;
    if (above < rank && rank <= incl) {
        unsigned cum = above;
        int bq = 0;
        #pragma unroll
        for (int q = 15; q >= 0; q--) {
            if (cum + v[q] >= rank) { bq = q; break; }
            cum += v[q];
        }
        *selb = (unsigned)(t * 16 + bq);
        *selr = rank - cum;
    }
    __syncthreads();
}

__device__ __forceinline__ int cell_of(float v) {
    int c = (int)((v + 3.0f) * (1.0f / 6.5f));
    if (c < 0) c = 0;
    if (c > NCELL - 1) c = NCELL - 1;
    return c;
}

__device__ __forceinline__ unsigned key_of(float m) {
    return (m >= 0.1f) ? __float_as_uint(m) : 0u;
}

// =====================================================================
// PART 1: scores -> keys -> radix select -> compact -> prefix -> scatter
// grid = 592 blocks (4 CTAs/SM exactly) for max bytes-in-flight
// =====================================================================
extern "C" __global__ void __launch_bounds__(NTH, 4)
k_part1(const float4* __restrict__ cls4, int n4)
{
    __shared__ unsigned sh[4096];
    __shared__ unsigned part[256];
    __shared__ unsigned sel_b, sel_rank;
    __shared__ unsigned long long s_M;

    int tid = threadIdx.x, bid = blockIdx.x;
    int gid = bid * NTH + tid;
    int lane = tid & 31;

    // ----- Phase A1: streaming max-reduce (class-outer) -----
    for (int i = tid; i < 4096; i += NTH) sh[i] = 0;
    __syncthreads();
    float4 mx[IPT];
    #pragma unroll
    for (int s = 0; s < IPT; s++) {
        int i = gid + s * NTOT1;
        mx[s] = (i < n4) ? cls4[i] : make_float4(0.f, 0.f, 0.f, 0.f);
    }
    #pragma unroll
    for (int c = 1; c < NCLS; c++) {
        const float4* row = cls4 + (size_t)c * n4;
        #pragma unroll
        for (int s = 0; s < IPT; s++) {
            int i = gid + s * NTOT1;
            if (i < n4) {
                float4 v = row[i];
                mx[s].x = fmaxf(mx[s].x, v.x);
                mx[s].y = fmaxf(mx[s].y, v.y);
                mx[s].z = fmaxf(mx[s].z, v.z);
                mx[s].w = fmaxf(mx[s].w, v.w);
            }
        }
    }
    // ----- Phase A2: hist1 (warp-aggregated) + exact kmax -----
    unsigned lkmax = 0;
    #pragma unroll
    for (int s = 0; s < IPT; s++) {
        int i = gid + s * NTOT1;
        if (i < n4) {
            unsigned kx = key_of(mx[s].x), ky = key_of(mx[s].y);
            unsigned kz = key_of(mx[s].z), kw = key_of(mx[s].w);
            lkmax = max(lkmax, max(max(kx, ky), max(kz, kw)));
            unsigned am = __activemask();
            unsigned mm;
            mm = __match_any_sync(am, kx >> 20);
            if (lane == __ffs(mm) - 1) atomicAdd(&sh[kx >> 20], __popc(mm));
            mm = __match_any_sync(am, ky >> 20);
            if (lane == __ffs(mm) - 1) atomicAdd(&sh[ky >> 20], __popc(mm));
            mm = __match_any_sync(am, kz >> 20);
            if (lane == __ffs(mm) - 1) atomicAdd(&sh[kz >> 20], __popc(mm));
            mm = __match_any_sync(am, kw >> 20);
            if (lane == __ffs(mm) - 1) atomicAdd(&sh[kw >> 20], __popc(mm));
        }
    }
    #pragma unroll
    for (int d = 16; d > 0; d >>= 1)
        lkmax = max(lkmax, __shfl_xor_sync(0xffffffffu, lkmax, d));
    if (lane == 0 && lkmax) atomicMax(&g_kmax, lkmax);
    __syncthreads();
    for (int b = tid; b < 4096; b += NTH) {
        unsigned c = sh[b];
        if (c) atomicAdd(&g_hist1[b], c);
    }
    gridsync(0, NBLK1);

    // ----- select1 (redundant per block) -----
    block_select(g_hist1, KPRE, part, &sel_b, &sel_rank);
    unsigned p1 = sel_b;
    unsigned rank2 = sel_rank;
    __syncthreads();

    // ----- Phase B: hist2 (keys recomputed from mx) -----
    for (int i = tid; i < 4096; i += NTH) sh[i] = 0;
    __syncthreads();
    #pragma unroll
    for (int s = 0; s < IPT; s++) {
        int i = gid + s * NTOT1;
        if (i < n4) {
            unsigned kx = key_of(mx[s].x), ky = key_of(mx[s].y);
            unsigned kz = key_of(mx[s].z), kw = key_of(mx[s].w);
            if ((kx >> 20) == p1) atomicAdd(&sh[(kx >> 8) & 0xFFFu], 1u);
            if ((ky >> 20) == p1) atomicAdd(&sh[(ky >> 8) & 0xFFFu], 1u);
            if ((kz >> 20) == p1) atomicAdd(&sh[(kz >> 8) & 0xFFFu], 1u);
            if ((kw >> 20) == p1) atomicAdd(&sh[(kw >> 8) & 0xFFFu], 1u);
        }
    }
    __syncthreads();
    for (int b = tid; b < 4096; b += NTH) {
        unsigned c = sh[b];
        if (c) atomicAdd(&g_hist2v[b], c);
    }
    gridsync(1, NBLK1);

    block_select(g_hist2v, rank2, part, &sel_b, &sel_rank);
    unsigned th = ((p1 << 12) | sel_b) << 8;   // bucket floor; sort absorbs ties
    if (tid == 0) {
        unsigned long long R = (unsigned long long)g_kmax - (unsigned long long)th + 1ull;
        if (R < 1ull) R = 1ull;
        s_M = ((unsigned long long)NBKT << 32) / R;   // monotonic fixed-point bucket map
    }
    __syncthreads();
    unsigned long long M = s_M;

    // ----- Phase C: compact (warp-aggregated alloc) + bucket count -----
    #pragma unroll
    for (int s = 0; s < IPT; s++) {
        int i = gid + s * NTOT1;
        if (i < n4) {
            unsigned kk[4];
            kk[0] = key_of(mx[s].x); kk[1] = key_of(mx[s].y);
            kk[2] = key_of(mx[s].z); kk[3] = key_of(mx[s].w);
            unsigned base4 = (unsigned)i * 4u;
            unsigned am = __activemask();
            #pragma unroll
            for (int l = 0; l < 4; l++) {
                unsigned key = kk[l];
                bool take = (key >= th);
                unsigned bal = __ballot_sync(am, take);
                if (bal) {
                    int leader = __ffs(bal) - 1;
                    unsigned basep = 0;
                    if (lane == leader) basep = atomicAdd(&g_ncand, (unsigned)__popc(bal));
                    basep = __shfl_sync(am, basep, leader);
                    if (take) {
                        unsigned pos = basep + (unsigned)__popc(bal & ((lane == 31) ? 0x7FFFFFFFu : ((1u << lane) - 1u)));
                        if (pos < CAND_MAX) {
                            g_cand[pos] = ((unsigned long long)key << 32) |
                                          (unsigned long long)(0xFFFFFFFFu - (base4 + (unsigned)l));
                            unsigned b = (unsigned)(((unsigned long long)(key - th) * M) >> 32);
                            if (b > NBKT - 1) b = NBKT - 1;
                            atomicAdd(&g_bcnt[NBKT - 1 - b], 1u);
                        }
                    }
                }
            }
        }
    }
    gridsync(2, NBLK1);

    // ----- Phase D2: prefix over NBKT (block 0) -----
    if (bid == 0) {
        unsigned loc[32];
        unsigned run = 0;
        #pragma unroll
        for (int q = 0; q < 32; q++) {
            unsigned vv = __ldcg(&g_bcnt[tid * 32 + q]);
            loc[q] = run; run += vv;
        }
        unsigned ws = run;
        #pragma unroll
        for (int d = 1; d < 32; d <<= 1) {
            unsigned v = __shfl_up_sync(0xffffffffu, ws, d);
            if (lane >= d) ws += v;
        }
        int wid = tid >> 5;
        if (lane == 31) part[wid] = ws;
        unsigned tpre = ws - run;
        __syncthreads();
        if (wid == 0 && lane < 8) {
            unsigned v = part[lane];
            #pragma unroll
            for (int d = 1; d < 8; d <<= 1) {
                unsigned u = __shfl_up_sync(0xffu, v, d);
                if (lane >= d) v += u;
            }
            part[lane] = v;
        }
        __syncthreads();
        unsigned wpre = (wid == 0) ? 0u : part[wid - 1];
        #pragma unroll
        for (int q = 0; q < 32; q++) g_bcnt[tid * 32 + q] = loc[q] + tpre + wpre;
    }
    gridsync(3, NBLK1);

    // ----- Phase D3: scatter; g_bcnt becomes per-bucket END -----
    unsigned cntv = __ldcg(&g_ncand);
    int cnt = (cntv > CAND_MAX) ? CAND_MAX : (int)cntv;
    for (int e = gid; e < cnt; e += NTOT1) {
        unsigned long long c = g_cand[e];
        unsigned key = (unsigned)(c >> 32);
        unsigned b = (unsigned)(((unsigned long long)(key - th) * M) >> 32);
        if (b > NBKT - 1) b = NBKT - 1;
        b = NBKT - 1 - b;
        unsigned pos = atomicAdd(&g_bcnt[b], 1u);
        g_sorted[pos] = c;
    }
}

// =====================================================================
// PART 2ab: bucket sort + gather + bin -> (gridsync) -> IoU edges
// =====================================================================
extern "C" __global__ void __launch_bounds__(NTH, 3)
k_p2ab(const float* __restrict__ boxes, const float* __restrict__ cls, int n)
{
    int tid = threadIdx.x;
    int gid = blockIdx.x * NTH + tid;
    unsigned cntv = __ldcg(&g_ncand);
    int cnt = (cntv > CAND_MAX) ? CAND_MAX : (int)cntv;

    // ----- per-bucket sort + emit + gather + bin + valid (fused) -----
    for (int b = gid; b < NBKT; b += NTOT2) {
        int st = (b == 0) ? 0 : (int)__ldcg(&g_bcnt[b - 1]);
        int en = (int)__ldcg(&g_bcnt[b]);
        for (int x = st + 1; x < en; x++) {
            unsigned long long v = g_sorted[x];
            int j = x - 1;
            while (j >= st && g_sorted[j] < v) { g_sorted[j + 1] = g_sorted[j]; j--; }
            g_sorted[j + 1] = v;
        }
        int lim = (en < KPRE) ? en : KPRE;
        for (int x = st; x < lim; x++) {
            unsigned long long c = g_sorted[x];
            unsigned key = (unsigned)(c >> 32);
            g_topkey[x] = key;
            if (key) {
                unsigned idx = 0xFFFFFFFFu - (unsigned)(c & 0xFFFFFFFFull);
                float x1 = boxes[idx];
                float y1 = boxes[(size_t)n + idx];
                float x2 = boxes[(size_t)2 * n + idx];
                float y2 = boxes[(size_t)3 * n + idx];
                float m = cls[idx];
                int lab = 0;
                #pragma unroll
                for (int cc = 1; cc < NCLS; cc++) {
                    float v = cls[(size_t)cc * n + idx];
                    if (v > m) { m = v; lab = cc; }   // first-max semantics
                }
                g_bx1[x] = x1; g_by1[x] = y1; g_bx2[x] = x2; g_by2[x] = y2;
                g_area[x] = __fmul_rn(fmaxf(__fsub_rn(x2, x1), 0.f), fmaxf(__fsub_rn(y2, y1), 0.f));
                g_lab[x] = lab;
                int cid = cell_of(y1) * NCELL + cell_of(x1);
                g_cellid[x] = cid;
                unsigned slot = atomicAdd(&g_cellcnt[cid], 1u);
                g_cellbox[cid * CELLCAP + slot] = (unsigned short)x;
                atomicOr(&g_valid[x >> 6], 1ull << (x & 63));
            } else {
                g_bx1[x] = g_by1[x] = g_bx2[x] = g_by2[x] = 0.f;
                g_area[x] = 0.f; g_lab[x] = 0; g_cellid[x] = -1;
            }
        }
    }
    for (int x = cnt + gid; x < KPRE; x += NTOT2) {
        g_topkey[x] = 0;
        g_bx1[x] = g_by1[x] = g_bx2[x] = g_by2[x] = 0.f;
        g_area[x] = 0.f; g_lab[x] = 0; g_cellid[x] = -1;
    }
    gridsync(4, NBLK2);

    // ----- IoU edges — 16 threads per row -----
    {
        int k = gid >> 4, sub = gid & 15;
        if (k < KPRE && g_topkey[k] != 0) {
            float x1 = g_bx1[k], y1 = g_by1[k], x2 = g_bx2[k], y2 = g_by2[k], a = g_area[k];
            int c = g_cellid[k];
            int cy = c / NCELL, cx = c % NCELL;
            int y0 = (cy > 0) ? cy - 1 : 0, y1c = (cy < NCELL - 1) ? cy + 1 : NCELL - 1;
            int x0 = (cx > 0) ? cx - 1 : 0, x1c = (cx < NCELL - 1) ? cx + 1 : NCELL - 1;
            for (int gy = y0; gy <= y1c; gy++) {
                for (int gx = x0; gx <= x1c; gx++) {
                    int cc = gy * NCELL + gx;
                    int e1 = (int)__ldcg(&g_cellcnt[cc]);
                    const unsigned short* cb = &g_cellbox[cc * CELLCAP];
                    for (int idx = sub; idx < e1; idx += 16) {
                        int j = cb[idx];
                        if (j > k) {
                            float iw = fmaxf(__fsub_rn(fminf(x2, g_bx2[j]), fmaxf(x1, g_bx1[j])), 0.f);
                            float ih = fmaxf(__fsub_rn(fminf(y2, g_by2[j]), fmaxf(y1, g_by1[j])), 0.f);
                            float inter = __fmul_rn(iw, ih);
                            float den = __fadd_rn(__fsub_rn(__fadd_rn(a, g_area[j]), inter), 1e-8f);
                            if (inter > __fmul_rn(0.5f, den)) {    // inter/den > 0.5 exactly
                                unsigned e = atomicAdd(&g_nedge, 1u);
                                if (e < EDGE_MAX_G)
                                    g_edges[e] = ((unsigned)k << 16) | (unsigned)j;
                            }
                        }
                    }
                }
            }
        }
    }
}

// =====================================================================
// PART 2c: SINGLE BLOCK — solve + finalize + cleanup (no grid syncs)
// =====================================================================
extern "C" __global__ void __launch_bounds__(1024, 1)
k_p2c(float* __restrict__ out)
{
    __shared__ unsigned sh[EDGE_SH];
    __shared__ unsigned long long sv[64], sp[64], snw[64], srn[64];
    __shared__ unsigned long long keepw[64];
    __shared__ unsigned baseb[64];
    __shared__ int schanged;

    int tid = threadIdx.x;
    const int nt = 1024;

    unsigned En = g_nedge;
    int E = (En > EDGE_MAX_G) ? EDGE_MAX_G : (int)En;
    bool inSh = (E <= EDGE_SH);
    if (tid < 64) { sv[tid] = g_valid[tid]; sp[tid] = 0ull; srn[tid] = 0ull; }
    __syncthreads();
    for (int e = tid; e < E; e += nt) {
        unsigned u = g_edges[e];
        if (inSh) sh[e] = u;
        int i = u >> 16;
        atomicOr(&srn[i >> 6], 1ull << (i & 63));
    }
    __syncthreads();
    const unsigned* ep = inSh ? (const unsigned*)sh : (const unsigned*)g_edges;

    // antitone fixed point; converged fixed point == greedy keep-set
    bool converged = false;
    for (int t = 0; t < 48 && !converged; t++) {
        if (tid < 64) snw[tid] = 0ull;
        if (tid == 0) schanged = 0;
        __syncthreads();
        for (int e = tid; e < E; e += nt) {
            unsigned u = ep[e];
            int i = u >> 16;
            if ((sv[i >> 6] & ~sp[i >> 6]) & (1ull << (i & 63))) {
                int j = u & 0xFFFF;
                atomicOr(&snw[j >> 6], 1ull << (j & 63));
            }
        }
        __syncthreads();
        if (tid < 64) {
            if (snw[tid] != sp[tid]) schanged = 1;
            sp[tid] = snw[tid];
        }
        __syncthreads();
        converged = (schanged == 0);
        __syncthreads();
    }
    if (!converged) {   // exact serial fallback (rarely taken)
        if (tid < 64) sp[tid] = 0ull;
        __syncthreads();
        for (int w = 0; w < 64; w++) {
            unsigned long long rb = srn[w] & sv[w];
            while (rb) {
                int b = __ffsll((long long)rb) - 1;
                rb &= rb - 1ull;
                int i = w * 64 + b;
                bool active = !((sp[w] >> b) & 1ull);
                if (active) {
                    for (int e = tid; e < E; e += nt) {
                        unsigned u = ep[e];
                        if ((int)(u >> 16) == i) {
                            int j = u & 0xFFFF;
                            atomicOr(&sp[j >> 6], 1ull << (j & 63));
                        }
                    }
                }
                __syncthreads();
            }
        }
    }
    if (tid < 64) keepw[tid] = sv[tid] & ~sp[tid];
    __syncthreads();
    if (tid == 0) {
        unsigned r = 0;
        for (int w = 0; w < 64; w++) { baseb[w] = r; r += __popcll(keepw[w]); }
    }
    __syncthreads();

    // ----- finalize: rank-inverse, one writer per output row -----
    if (tid < KPOST) {
        unsigned r = (unsigned)tid;
        int lo = 0, hi = 63;
        while (lo < hi) {
            int mid = (lo + hi + 1) >> 1;
            if (baseb[mid] <= r) lo = mid; else hi = mid - 1;
        }
        unsigned long long kp = keepw[lo];
        unsigned within = r - baseb[lo];
        float* row = out + (size_t)r * 6;
        if (within < (unsigned)__popcll(kp)) {
            unsigned long long m = kp;
            for (unsigned q = 0; q < within; q++) m &= m - 1ull;
            int k = lo * 64 + (__ffsll((long long)m) - 1);
            row[0] = g_bx1[k];
            row[1] = g_by1[k];
            row[2] = g_bx2[k];
            row[3] = g_by2[k];
            row[4] = __uint_as_float(g_topkey[k]);
            row[5] = (float)g_lab[k];
        } else {
            row[0] = row[1] = row[2] = row[3] = row[4] = row[5] = 0.f;
        }
    }

    // ----- cleanup: restore all mutable state for the next graph replay -----
    for (int i = tid; i < 4096; i += nt) { g_hist1[i] = 0; g_hist2v[i] = 0; }
    for (int i = tid; i < NBKT; i += nt) g_bcnt[i] = 0;
    for (int i = tid; i < NCELLS; i += nt) g_cellcnt[i] = 0;
    if (tid < 64) g_valid[tid] = 0ull;
    if (tid == 0) { g_ncand = 0; g_kmax = 0; g_nedge = 0; }
    __syncthreads();
    if (tid == 0) {
        for (int i = 0; i < 8; i++) g_sync[i] = 0;
        __threadfence();
    }
}

extern "C" void kernel_launch(void* const* d_in, const int* in_sizes, int n_in,
                              void* d_out, int out_size) {
    const float* a0 = (const float*)d_in[0];
    const float* a1 = (const float*)d_in[1];
    const float* boxes;
    const float* cls;
    int bsz;
    if (in_sizes[0] <= in_sizes[1]) { boxes = a0; cls = a1; bsz = in_sizes[0]; }
    else                            { boxes = a1; cls = a0; bsz = in_sizes[1]; }
    int n = bsz / 4;
    if (n > NB) n = NB;
    int n4 = n / 4;
    float* out = (float*)d_out;

    k_part1<<<NBLK1, NTH>>>((const float4*)cls, n4);
    k_p2ab<<<NBLK2, NTH>>>(boxes, cls, n);
    k_p2c<<<1, 1024>>>(out);
}

// round 17
// speedup vs baseline: 1.0915x; 1.0915x over previous
#include <cuda_runtime.h>

#define NB 2000000
#define NCLS 10
#define KPRE 4096
#define KPOST 500
#define CAND_MAX 8192
#define NBKT 8192
#define NCELL 17
#define NCELLS (NCELL * NCELL)
#define CELLCAP 4096
#define EDGE_MAX_G 262144
#define EDGE_SH 4096
#define NTH 256
#define NBLK 400
#define NTOT (NBLK * NTH)
#define IPT 5

// -------- global scratch (zero-init at load; restored by in-kernel cleanup) --------
static __device__ unsigned g_hist1[4096];
static __device__ unsigned g_hist2v[4096];
static __device__ unsigned g_bcnt[NBKT];
static __device__ unsigned g_cellcnt[NCELLS];
static __device__ unsigned long long g_sorted[CAND_MAX];
static __device__ unsigned g_ncand, g_kmax, g_nedge;
static __device__ unsigned long long g_cand[CAND_MAX];
static __device__ unsigned g_topkey[KPRE];
static __device__ float g_bx1[KPRE], g_by1[KPRE], g_bx2[KPRE], g_by2[KPRE], g_area[KPRE];
static __device__ int g_lab[KPRE];
static __device__ unsigned long long g_valid[64];
static __device__ int g_cellid[KPRE];
static __device__ unsigned short g_cellbox[NCELLS * CELLCAP];
static __device__ unsigned g_edges[EDGE_MAX_G];
static __device__ volatile unsigned g_sync[8];

// grid barrier; all blocks co-resident (enforced by __launch_bounds__ + grid size)
__device__ __forceinline__ void gridsync(int id, int nblk) {
    __syncthreads();
    if (threadIdx.x == 0) {
        __threadfence();
        atomicAdd((unsigned*)&g_sync[id], 1u);
        unsigned ns = 64;
        while (g_sync[id] < (unsigned)nblk) {
            __nanosleep(ns);
            if (ns < 512) ns <<= 1;
        }
        __threadfence();
    }
    __syncthreads();
}

// block-level "find bucket containing rank (counted from top)" over a 4096 histogram
__device__ __forceinline__ void block_select(const unsigned* __restrict__ gh, unsigned rank,
                                             unsigned* part, unsigned* selb, unsigned* selr) {
    int t = threadIdx.x;
    if (t == 0) { *selb = 0; *selr = 1; }
    unsigned v[16];
    unsigned s = 0;
    #pragma unroll
    for (int q = 0; q < 16; q++) { v[q] = gh[t * 16 + q]; s += v[q]; }
    part[t] = s;
    __syncthreads();
    for (int d = 1; d < 256; d <<= 1) {
        unsigned x = part[t] + ((t + d < 256) ? part[t + d] : 0u);
        __syncthreads();
        part[t] = x;
        __syncthreads();
    }
    unsigned incl = part[t];
    unsigned above = incl - s;
    if (above < rank && rank <= incl) {
        unsigned cum = above;
        int bq = 0;
        #pragma unroll
        for (int q = 15; q >= 0; q--) {
            if (cum + v[q] >= rank) { bq = q; break; }
            cum += v[q];
        }
        *selb = (unsigned)(t * 16 + bq);
        *selr = rank - cum;
    }
    __syncthreads();
}

__device__ __forceinline__ int cell_of(float v) {
    int c = (int)((v + 3.0f) * (1.0f / 6.5f));
    if (c < 0) c = 0;
    if (c > NCELL - 1) c = NCELL - 1;
    return c;
}

// =====================================================================
// PART 1 (R12 config): lb(256,3), grid 400, IPT 5, kv cached in registers
// =====================================================================
extern "C" __global__ void __launch_bounds__(NTH, 3)
k_part1(const float4* __restrict__ cls4, int n4)
{
    __shared__ unsigned sh[4096];
    __shared__ unsigned part[256];
    __shared__ unsigned sel_b, sel_rank;
    __shared__ unsigned long long s_M;

    int tid = threadIdx.x, bid = blockIdx.x;
    int gid = bid * NTH + tid;
    int lane = tid & 31;

    // ----- Phase A: scores -> keys (registers) + warp-agg hist1 + exact kmax -----
    for (int i = tid; i < 4096; i += NTH) sh[i] = 0;
    __syncthreads();
    uint4 kv[IPT];
    unsigned lkmax = 0;
    #pragma unroll
    for (int s = 0; s < IPT; s++) {
        int i = gid + s * NTOT;
        uint4 k = make_uint4(0, 0, 0, 0);
        if (i < n4) {
            float4 m = cls4[i];
            #pragma unroll
            for (int c = 1; c < NCLS; c++) {
                float4 v = cls4[(size_t)c * n4 + i];
                m.x = fmaxf(m.x, v.x); m.y = fmaxf(m.y, v.y);
                m.z = fmaxf(m.z, v.z); m.w = fmaxf(m.w, v.w);
            }
            k.x = (m.x >= 0.1f) ? __float_as_uint(m.x) : 0u;
            k.y = (m.y >= 0.1f) ? __float_as_uint(m.y) : 0u;
            k.z = (m.z >= 0.1f) ? __float_as_uint(m.z) : 0u;
            k.w = (m.w >= 0.1f) ? __float_as_uint(m.w) : 0u;
            lkmax = max(lkmax, max(max(k.x, k.y), max(k.z, k.w)));
            unsigned am = __activemask();
            unsigned mm;
            mm = __match_any_sync(am, k.x >> 20);
            if (lane == __ffs(mm) - 1) atomicAdd(&sh[k.x >> 20], __popc(mm));
            mm = __match_any_sync(am, k.y >> 20);
            if (lane == __ffs(mm) - 1) atomicAdd(&sh[k.y >> 20], __popc(mm));
            mm = __match_any_sync(am, k.z >> 20);
            if (lane == __ffs(mm) - 1) atomicAdd(&sh[k.z >> 20], __popc(mm));
            mm = __match_any_sync(am, k.w >> 20);
            if (lane == __ffs(mm) - 1) atomicAdd(&sh[k.w >> 20], __popc(mm));
        }
        kv[s] = k;
    }
    #pragma unroll
    for (int d = 16; d > 0; d >>= 1)
        lkmax = max(lkmax, __shfl_xor_sync(0xffffffffu, lkmax, d));
    if (lane == 0 && lkmax) atomicMax(&g_kmax, lkmax);
    __syncthreads();
    for (int b = tid; b < 4096; b += NTH) {
        unsigned c = sh[b];
        if (c) atomicAdd(&g_hist1[b], c);
    }
    gridsync(0, NBLK);

    // ----- select1 (redundant per block) -----
    block_select(g_hist1, KPRE, part, &sel_b, &sel_rank);
    unsigned p1 = sel_b;
    unsigned rank2 = sel_rank;
    __syncthreads();

    // ----- Phase B: hist2 from register keys -----
    for (int i = tid; i < 4096; i += NTH) sh[i] = 0;
    __syncthreads();
    #pragma unroll
    for (int s = 0; s < IPT; s++) {
        int i = gid + s * NTOT;
        if (i < n4) {
            uint4 k = kv[s];
            if ((k.x >> 20) == p1) atomicAdd(&sh[(k.x >> 8) & 0xFFFu], 1u);
            if ((k.y >> 20) == p1) atomicAdd(&sh[(k.y >> 8) & 0xFFFu], 1u);
            if ((k.z >> 20) == p1) atomicAdd(&sh[(k.z >> 8) & 0xFFFu], 1u);
            if ((k.w >> 20) == p1) atomicAdd(&sh[(k.w >> 8) & 0xFFFu], 1u);
        }
    }
    __syncthreads();
    for (int b = tid; b < 4096; b += NTH) {
        unsigned c = sh[b];
        if (c) atomicAdd(&g_hist2v[b], c);
    }
    gridsync(1, NBLK);

    block_select(g_hist2v, rank2, part, &sel_b, &sel_rank);
    unsigned th = ((p1 << 12) | sel_b) << 8;   // bucket floor; sort absorbs ties
    if (tid == 0) {
        unsigned long long R = (unsigned long long)g_kmax - (unsigned long long)th + 1ull;
        if (R < 1ull) R = 1ull;
        s_M = ((unsigned long long)NBKT << 32) / R;   // monotonic fixed-point bucket map
    }
    __syncthreads();
    unsigned long long M = s_M;

    // ----- Phase C: compact (warp-aggregated alloc) + bucket count -----
    #pragma unroll
    for (int s = 0; s < IPT; s++) {
        int i = gid + s * NTOT;
        if (i < n4) {
            uint4 k = kv[s];
            unsigned base4 = (unsigned)i * 4u;
            unsigned am = __activemask();
            #pragma unroll
            for (int l = 0; l < 4; l++) {
                unsigned key = (l == 0) ? k.x : (l == 1) ? k.y : (l == 2) ? k.z : k.w;
                bool take = (key >= th);
                unsigned bal = __ballot_sync(am, take);
                if (bal) {
                    int leader = __ffs(bal) - 1;
                    unsigned basep = 0;
                    if (lane == leader) basep = atomicAdd(&g_ncand, (unsigned)__popc(bal));
                    basep = __shfl_sync(am, basep, leader);
                    if (take) {
                        unsigned pos = basep + (unsigned)__popc(bal & ((lane == 31) ? 0x7FFFFFFFu : ((1u << lane) - 1u)));
                        if (pos < CAND_MAX) {
                            g_cand[pos] = ((unsigned long long)key << 32) |
                                          (unsigned long long)(0xFFFFFFFFu - (base4 + (unsigned)l));
                            unsigned b = (unsigned)(((unsigned long long)(key - th) * M) >> 32);
                            if (b > NBKT - 1) b = NBKT - 1;
                            atomicAdd(&g_bcnt[NBKT - 1 - b], 1u);
                        }
                    }
                }
            }
        }
    }
    gridsync(2, NBLK);

    // ----- Phase D2: prefix over NBKT (block 0) -----
    if (bid == 0) {
        unsigned loc[32];
        unsigned run = 0;
        #pragma unroll
        for (int q = 0; q < 32; q++) {
            unsigned vv = __ldcg(&g_bcnt[tid * 32 + q]);
            loc[q] = run; run += vv;
        }
        unsigned ws = run;
        #pragma unroll
        for (int d = 1; d < 32; d <<= 1) {
            unsigned v = __shfl_up_sync(0xffffffffu, ws, d);
            if (lane >= d) ws += v;
        }
        int wid = tid >> 5;
        if (lane == 31) part[wid] = ws;
        unsigned tpre = ws - run;
        __syncthreads();
        if (wid == 0 && lane < 8) {
            unsigned v = part[lane];
            #pragma unroll
            for (int d = 1; d < 8; d <<= 1) {
                unsigned u = __shfl_up_sync(0xffu, v, d);
                if (lane >= d) v += u;
            }
            part[lane] = v;
        }
        __syncthreads();
        unsigned wpre = (wid == 0) ? 0u : part[wid - 1];
        #pragma unroll
        for (int q = 0; q < 32; q++) g_bcnt[tid * 32 + q] = loc[q] + tpre + wpre;
    }
    gridsync(3, NBLK);

    // ----- Phase D3: scatter; g_bcnt becomes per-bucket END -----
    unsigned cntv = __ldcg(&g_ncand);
    int cnt = (cntv > CAND_MAX) ? CAND_MAX : (int)cntv;
    for (int e = gid; e < cnt; e += NTOT) {
        unsigned long long c = g_cand[e];
        unsigned key = (unsigned)(c >> 32);
        unsigned b = (unsigned)(((unsigned long long)(key - th) * M) >> 32);
        if (b > NBKT - 1) b = NBKT - 1;
        b = NBKT - 1 - b;
        unsigned pos = atomicAdd(&g_bcnt[b], 1u);
        g_sorted[pos] = c;
    }
}

// =====================================================================
// PART 2ab: bucket sort + gather + bin -> (gridsync) -> IoU edges
// =====================================================================
extern "C" __global__ void __launch_bounds__(NTH, 3)
k_p2ab(const float* __restrict__ boxes, const float* __restrict__ cls, int n)
{
    int tid = threadIdx.x;
    int gid = blockIdx.x * NTH + tid;
    unsigned cntv = __ldcg(&g_ncand);
    int cnt = (cntv > CAND_MAX) ? CAND_MAX : (int)cntv;

    // ----- per-bucket sort + emit + gather + bin + valid (fused) -----
    for (int b = gid; b < NBKT; b += NTOT) {
        int st = (b == 0) ? 0 : (int)__ldcg(&g_bcnt[b - 1]);
        int en = (int)__ldcg(&g_bcnt[b]);
        for (int x = st + 1; x < en; x++) {
            unsigned long long v = g_sorted[x];
            int j = x - 1;
            while (j >= st && g_sorted[j] < v) { g_sorted[j + 1] = g_sorted[j]; j--; }
            g_sorted[j + 1] = v;
        }
        int lim = (en < KPRE) ? en : KPRE;
        for (int x = st; x < lim; x++) {
            unsigned long long c = g_sorted[x];
            unsigned key = (unsigned)(c >> 32);
            g_topkey[x] = key;
            if (key) {
                unsigned idx = 0xFFFFFFFFu - (unsigned)(c & 0xFFFFFFFFull);
                float x1 = boxes[idx];
                float y1 = boxes[(size_t)n + idx];
                float x2 = boxes[(size_t)2 * n + idx];
                float y2 = boxes[(size_t)3 * n + idx];
                float m = cls[idx];
                int lab = 0;
                #pragma unroll
                for (int cc = 1; cc < NCLS; cc++) {
                    float v = cls[(size_t)cc * n + idx];
                    if (v > m) { m = v; lab = cc; }   // first-max semantics
                }
                g_bx1[x] = x1; g_by1[x] = y1; g_bx2[x] = x2; g_by2[x] = y2;
                g_area[x] = __fmul_rn(fmaxf(__fsub_rn(x2, x1), 0.f), fmaxf(__fsub_rn(y2, y1), 0.f));
                g_lab[x] = lab;
                int cid = cell_of(y1) * NCELL + cell_of(x1);
                g_cellid[x] = cid;
                unsigned slot = atomicAdd(&g_cellcnt[cid], 1u);
                g_cellbox[cid * CELLCAP + slot] = (unsigned short)x;
                atomicOr(&g_valid[x >> 6], 1ull << (x & 63));
            } else {
                g_bx1[x] = g_by1[x] = g_bx2[x] = g_by2[x] = 0.f;
                g_area[x] = 0.f; g_lab[x] = 0; g_cellid[x] = -1;
            }
        }
    }
    for (int x = cnt + gid; x < KPRE; x += NTOT) {
        g_topkey[x] = 0;
        g_bx1[x] = g_by1[x] = g_bx2[x] = g_by2[x] = 0.f;
        g_area[x] = 0.f; g_lab[x] = 0; g_cellid[x] = -1;
    }
    gridsync(4, NBLK);

    // ----- IoU edges — 16 threads per row -----
    {
        int k = gid >> 4, sub = gid & 15;
        if (k < KPRE && g_topkey[k] != 0) {
            float x1 = g_bx1[k], y1 = g_by1[k], x2 = g_bx2[k], y2 = g_by2[k], a = g_area[k];
            int c = g_cellid[k];
            int cy = c / NCELL, cx = c % NCELL;
            int y0 = (cy > 0) ? cy - 1 : 0, y1c = (cy < NCELL - 1) ? cy + 1 : NCELL - 1;
            int x0 = (cx > 0) ? cx - 1 : 0, x1c = (cx < NCELL - 1) ? cx + 1 : NCELL - 1;
            for (int gy = y0; gy <= y1c; gy++) {
                for (int gx = x0; gx <= x1c; gx++) {
                    int cc = gy * NCELL + gx;
                    int e1 = (int)__ldcg(&g_cellcnt[cc]);
                    const unsigned short* cb = &g_cellbox[cc * CELLCAP];
                    for (int idx = sub; idx < e1; idx += 16) {
                        int j = cb[idx];
                        if (j > k) {
                            float iw = fmaxf(__fsub_rn(fminf(x2, g_bx2[j]), fmaxf(x1, g_bx1[j])), 0.f);
                            float ih = fmaxf(__fsub_rn(fminf(y2, g_by2[j]), fmaxf(y1, g_by1[j])), 0.f);
                            float inter = __fmul_rn(iw, ih);
                            float den = __fadd_rn(__fsub_rn(__fadd_rn(a, g_area[j]), inter), 1e-8f);
                            if (inter > __fmul_rn(0.5f, den)) {    // inter/den > 0.5 exactly
                                unsigned e = atomicAdd(&g_nedge, 1u);
                                if (e < EDGE_MAX_G)
                                    g_edges[e] = ((unsigned)k << 16) | (unsigned)j;
                            }
                        }
                    }
                }
            }
        }
    }
}

// =====================================================================
// PART 2c: SINGLE BLOCK — solve + finalize + cleanup (no grid syncs)
// =====================================================================
extern "C" __global__ void __launch_bounds__(1024, 1)
k_p2c(float* __restrict__ out)
{
    __shared__ unsigned sh[EDGE_SH];
    __shared__ unsigned long long sv[64], sp[64], snw[64], srn[64];
    __shared__ unsigned long long keepw[64];
    __shared__ unsigned baseb[64];
    __shared__ int schanged;

    int tid = threadIdx.x;
    const int nt = 1024;

    unsigned En = g_nedge;
    int E = (En > EDGE_MAX_G) ? EDGE_MAX_G : (int)En;
    bool inSh = (E <= EDGE_SH);
    if (tid < 64) { sv[tid] = g_valid[tid]; sp[tid] = 0ull; srn[tid] = 0ull; }
    __syncthreads();
    for (int e = tid; e < E; e += nt) {
        unsigned u = g_edges[e];
        if (inSh) sh[e] = u;
        int i = u >> 16;
        atomicOr(&srn[i >> 6], 1ull << (i & 63));
    }
    __syncthreads();
    const unsigned* ep = inSh ? (const unsigned*)sh : (const unsigned*)g_edges;

    // antitone fixed point; converged fixed point == greedy keep-set
    bool converged = false;
    for (int t = 0; t < 48 && !converged; t++) {
        if (tid < 64) snw[tid] = 0ull;
        if (tid == 0) schanged = 0;
        __syncthreads();
        for (int e = tid; e < E; e += nt) {
            unsigned u = ep[e];
            int i = u >> 16;
            if ((sv[i >> 6] & ~sp[i >> 6]) & (1ull << (i & 63))) {
                int j = u & 0xFFFF;
                atomicOr(&snw[j >> 6], 1ull << (j & 63));
            }
        }
        __syncthreads();
        if (tid < 64) {
            if (snw[tid] != sp[tid]) schanged = 1;
            sp[tid] = snw[tid];
        }
        __syncthreads();
        converged = (schanged == 0);
        __syncthreads();
    }
    if (!converged) {   // exact serial fallback (rarely taken)
        if (tid < 64) sp[tid] = 0ull;
        __syncthreads();
        for (int w = 0; w < 64; w++) {
            unsigned long long rb = srn[w] & sv[w];
            while (rb) {
                int b = __ffsll((long long)rb) - 1;
                rb &= rb - 1ull;
                int i = w * 64 + b;
                bool active = !((sp[w] >> b) & 1ull);
                if (active) {
                    for (int e = tid; e < E; e += nt) {
                        unsigned u = ep[e];
                        if ((int)(u >> 16) == i) {
                            int j = u & 0xFFFF;
                            atomicOr(&sp[j >> 6], 1ull << (j & 63));
                        }
                    }
                }
                __syncthreads();
            }
        }
    }
    if (tid < 64) keepw[tid] = sv[tid] & ~sp[tid];
    __syncthreads();
    if (tid == 0) {
        unsigned r = 0;
        for (int w = 0; w < 64; w++) { baseb[w] = r; r += __popcll(keepw[w]); }
    }
    __syncthreads();

    // ----- finalize: rank-inverse, one writer per output row -----
    if (tid < KPOST) {
        unsigned r = (unsigned)tid;
        int lo = 0, hi = 63;
        while (lo < hi) {
            int mid = (lo + hi + 1) >> 1;
            if (baseb[mid] <= r) lo = mid; else hi = mid - 1;
        }
        unsigned long long kp = keepw[lo];
        unsigned within = r - baseb[lo];
        float* row = out + (size_t)r * 6;
        if (within < (unsigned)__popcll(kp)) {
            unsigned long long m = kp;
            for (unsigned q = 0; q < within; q++) m &= m - 1ull;
            int k = lo * 64 + (__ffsll((long long)m) - 1);
            row[0] = g_bx1[k];
            row[1] = g_by1[k];
            row[2] = g_bx2[k];
            row[3] = g_by2[k];
            row[4] = __uint_as_float(g_topkey[k]);
            row[5] = (float)g_lab[k];
        } else {
            row[0] = row[1] = row[2] = row[3] = row[4] = row[5] = 0.f;
        }
    }

    // ----- cleanup: restore all mutable state for the next graph replay -----
    for (int i = tid; i < 4096; i += nt) { g_hist1[i] = 0; g_hist2v[i] = 0; }
    for (int i = tid; i < NBKT; i += nt) g_bcnt[i] = 0;
    for (int i = tid; i < NCELLS; i += nt) g_cellcnt[i] = 0;
    if (tid < 64) g_valid[tid] = 0ull;
    if (tid == 0) { g_ncand = 0; g_kmax = 0; g_nedge = 0; }
    __syncthreads();
    if (tid == 0) {
        for (int i = 0; i < 8; i++) g_sync[i] = 0;
        __threadfence();
    }
}

extern "C" void kernel_launch(void* const* d_in, const int* in_sizes, int n_in,
                              void* d_out, int out_size) {
    const float* a0 = (const float*)d_in[0];
    const float* a1 = (const float*)d_in[1];
    const float* boxes;
    const float* cls;
    int bsz;
    if (in_sizes[0] <= in_sizes[1]) { boxes = a0; cls = a1; bsz = in_sizes[0]; }
    else                            { boxes = a1; cls = a0; bsz = in_sizes[1]; }
    int n = bsz / 4;
    if (n > NB) n = NB;
    int n4 = n / 4;
    float* out = (float*)d_out;

    k_part1<<<NBLK, NTH>>>((const float4*)cls, n4);
    k_p2ab<<<NBLK, NTH>>>(boxes, cls, n);
    k_p2c<<<1, 1024>>>(out);
}